// round 2
// baseline (speedup 1.0000x reference)
#include <cuda_runtime.h>
#include <cstdint>
#include <math.h>

// ---------------- problem constants ----------------
#define BATCH   4
#define NPIX    2048
#define NBINS   4096
#define KT      250
#define NREP    64
#define TSIM    3846          // (NBINS - KT + 1) - 1
#define NCHAIN  (BATCH*NREP)  // 256
#define TPAD    3872
#define PCHUNKS 16
#define PPER    (NPIX/PCHUNKS) // 128

// JAX threefry mode: 1 = jax_threefry_partitionable (modern default), 0 = legacy
#define RNG_PARTITIONABLE 1

// ---------------- scratch (no allocations allowed) ----------------
__device__ float    d_partial[PCHUNKS][BATCH*NBINS]; // 1 MiB
__device__ float    d_g[BATCH*TPAD];                 // gensig
__device__ uint32_t d_keys[TSIM*2];                  // per-step PRNG keys
__device__ float    d_C[NCHAIN*TPAD];                // logit thresholds, [chain][t]

// ---------------- threefry2x32 (JAX constants, 20 rounds) ----------------
__device__ __forceinline__ void tf2x32(uint32_t k0, uint32_t k1,
                                       uint32_t x0, uint32_t x1,
                                       uint32_t &o0, uint32_t &o1) {
    uint32_t k2 = k0 ^ k1 ^ 0x1BD11BDAu;
#define ROTL(v,s) (((v)<<(s))|((v)>>(32-(s))))
#define RND(r) { x0 += x1; x1 = ROTL(x1,(r)); x1 ^= x0; }
    x0 += k0; x1 += k1;
    RND(13) RND(15) RND(26) RND(6)
    x0 += k1; x1 += k2 + 1u;
    RND(17) RND(29) RND(16) RND(24)
    x0 += k2; x1 += k0 + 2u;
    RND(13) RND(15) RND(26) RND(6)
    x0 += k0; x1 += k1 + 3u;
    RND(17) RND(29) RND(16) RND(24)
    x0 += k1; x1 += k2 + 4u;
    RND(13) RND(15) RND(26) RND(6)
    x0 += k2; x1 += k0 + 5u;
    o0 = x0; o1 = x1;
#undef RND
#undef ROTL
}

// ---------------- K1: spatial projection partials ----------------
// grid (tTile=4, pChunk=16, b=4), block 256. Each thread: float4 over t.
__global__ void k_proj(const float* __restrict__ stim, const float* __restrict__ w) {
    int b  = blockIdx.z;
    int pc = blockIdx.y;
    int t0 = blockIdx.x * 1024 + threadIdx.x * 4;
    const float* base = stim + ((size_t)b * NPIX + (size_t)pc * PPER) * NBINS + t0;

    __shared__ float ws[PPER];
    for (int i = threadIdx.x; i < PPER; i += 256) ws[i] = w[pc * PPER + i];
    __syncthreads();

    float4 acc = make_float4(0.f, 0.f, 0.f, 0.f);
#pragma unroll 8
    for (int p = 0; p < PPER; ++p) {
        float4 v = *(const float4*)(base + (size_t)p * NBINS);
        float  c = ws[p];
        acc.x += c * v.x; acc.y += c * v.y; acc.z += c * v.z; acc.w += c * v.w;
    }
    *(float4*)(&d_partial[pc][b * NBINS + t0]) = acc;
}

// ---------------- K2: reduce partials + temporal conv (fp64 accumulate) ----------------
// grid (8 t-chunks, 4 b), block 512
#define CCH 482
__global__ void k_conv(const float* __restrict__ tc, const float* __restrict__ bias) {
    int b  = blockIdx.y;
    int t0 = blockIdx.x * CCH;
    int cnt  = min(CCH, TSIM - t0);
    if (cnt <= 0) return;
    int need = cnt + KT - 1;

    __shared__ float sps[CCH + KT];  // 732
    __shared__ float tcs[KT];
    for (int i = threadIdx.x; i < need; i += blockDim.x) {
        float s = 0.f;
        int idx = b * NBINS + t0 + i;
#pragma unroll
        for (int pc = 0; pc < PCHUNKS; ++pc) s += d_partial[pc][idx];
        sps[i] = s;
    }
    for (int i = threadIdx.x; i < KT; i += blockDim.x) tcs[i] = tc[i];
    __syncthreads();

    double bs = (double)bias[0];
    for (int t = threadIdx.x; t < cnt; t += blockDim.x) {
        double a0 = 0.0, a1 = 0.0;
#pragma unroll 2
        for (int k = 0; k < KT; k += 2) {
            a0 += (double)sps[t + k]     * (double)tcs[k];
            a1 += (double)sps[t + k + 1] * (double)tcs[k + 1];
        }
        d_g[b * TPAD + t0 + t] = (float)(a0 + a1 + bs);
    }
}

// ---------------- K3: per-step keys = split(key(42), TSIM) ----------------
__global__ void k_keys() {
    int t = blockIdx.x * 256 + threadIdx.x;
    if (t >= TSIM) return;
    uint32_t o0, o1;
#if RNG_PARTITIONABLE
    tf2x32(0u, 42u, 0u, (uint32_t)t, o0, o1);
    d_keys[2*t]   = o0;
    d_keys[2*t+1] = o1;
#else
    // legacy split: concat(word0 of pairs, word1 of pairs).reshape(n,2)
    uint32_t a, c;
    int j0 = 2*t, j1 = 2*t + 1;
    if (j0 < TSIM) { tf2x32(0u,42u,(uint32_t)j0,(uint32_t)(j0+TSIM),o0,o1); a = o0; }
    else           { tf2x32(0u,42u,(uint32_t)(j0-TSIM),(uint32_t)j0,o0,o1); a = o1; }
    if (j1 < TSIM) { tf2x32(0u,42u,(uint32_t)j1,(uint32_t)(j1+TSIM),o0,o1); c = o0; }
    else           { tf2x32(0u,42u,(uint32_t)(j1-TSIM),(uint32_t)j1,o0,o1); c = o1; }
    d_keys[2*t]   = a;
    d_keys[2*t+1] = c;
#endif
}

// ---------------- K4: thresholds c[i][t] = logit(uniform) ----------------
// grid (ceil(TSIM/128), NCHAIN), block 128
__global__ void k_thresh() {
    int t = blockIdx.x * 128 + threadIdx.x;
    int i = blockIdx.y;
    if (t >= TSIM) return;
    uint32_t k0 = d_keys[2*t], k1 = d_keys[2*t+1];
    uint32_t bits, o0, o1;
#if RNG_PARTITIONABLE
    tf2x32(k0, k1, 0u, (uint32_t)i, o0, o1);
    bits = o0 ^ o1;
#else
    if (i < 128) { tf2x32(k0, k1, (uint32_t)i,        (uint32_t)(i+128), o0, o1); bits = o0; }
    else         { tf2x32(k0, k1, (uint32_t)(i-128),  (uint32_t)i,       o0, o1); bits = o1; }
#endif
    float u = __uint_as_float((bits >> 9) | 0x3f800000u) - 1.0f;
    // spike  <=>  (g + fb) > logit(u).  u==0 -> -inf (always spike), matches u<rate.
    double du = (double)u;
    d_C[i * TPAD + t] = (float)(log(du) - log1p(-du));
}

// ---------------- K5: sequential simulation, warp per chain ----------------
// grid 256, block 32. Chunked: parallel "old-spike" dot + sequential intra-chunk resolve.
__global__ void __launch_bounds__(32, 8)
k_sim(const float* __restrict__ initial, const float* __restrict__ fbfilt,
      float* __restrict__ out) {
    int chain = blockIdx.x;          // b*64 + r
    int b     = chain >> 6;
    int lane  = threadIdx.x;

    __shared__ float hist[KT + TSIM];   // full spike history, 4096 floats
    __shared__ float fsm[320];          // feedback filter, zero padded

    for (int k = lane; k < 320; k += 32) fsm[k] = (k < KT) ? fbfilt[k] : 0.0f;
    for (int k = lane; k < KT; k += 32) {
        float v = initial[b * KT + k];
        hist[k] = v;
        out[(size_t)chain * NBINS + k] = v;
    }
    __syncwarp();

    const float* gp = d_g + b * TPAD;
    const float* cp = d_C + chain * TPAD;
    float*       op = out + (size_t)chain * NBINS + KT;
    const int    nmax = 249 - lane;     // lane l computes 250-l "old" terms

    for (int t0 = 0; t0 < TSIM; t0 += 32) {
        int len = TSIM - t0; if (len > 32) len = 32;
        float gl = (lane < len) ? gp[t0 + lane] : 0.0f;
        float cl = (lane < len) ? cp[t0 + lane] : __int_as_float(0x7f800000); // +inf

        // Phase A (parallel): contributions from spikes emitted before t0.
        // lane l, step t=t0+l:  sum_{m=0}^{249-l} hist[KT + t0 - 1 - m] * f[249-l-m]
        float acc = 0.0f;
        const float* hp = hist + KT + t0 - 1;  // broadcast reads across lanes
        const float* fp = fsm + nmax;
#pragma unroll 4
        for (int m = 0; m <= nmax; ++m)
            acc += hp[-m] * fp[-m];
        float base = gl + acc;

        // Phase B (sequential): resolve intra-chunk feedback, 1 ballot + 1 FMA per step
        float    fbn    = 0.0f;
        unsigned spikes = 0u;
#pragma unroll
        for (int m = 0; m < 32; ++m) {
            float x = base + fbn;
            unsigned bal = __ballot_sync(0xffffffffu, x > cl);
            unsigned bit = (bal >> m) & 1u;
            spikes |= bit << m;
            if (lane > m && bit) fbn += fsm[250 - lane + m];
        }

        float spf = (float)((spikes >> lane) & 1u);
        if (lane < len) {
            hist[KT + t0 + lane] = spf;
            op[t0 + lane]        = spf;
        }
        __syncwarp();
    }
}

// ---------------- launch ----------------
extern "C" void kernel_launch(void* const* d_in, const int* in_sizes, int n_in,
                              void* d_out, int out_size) {
    const float* stim = (const float*)d_in[0];  // (4,2048,4096)
    const float* init = (const float*)d_in[1];  // (4,250)
    const float* spat = (const float*)d_in[2];  // (2048,)
    const float* tc   = (const float*)d_in[3];  // (250,)
    const float* fbf  = (const float*)d_in[4];  // (250,)
    const float* bias = (const float*)d_in[5];  // (1,)
    float* out = (float*)d_out;                 // (4,64,4096) f32

    dim3 g1(4, 16, 4);
    k_proj<<<g1, 256>>>(stim, spat);
    dim3 g2(8, 4);
    k_conv<<<g2, 512>>>(tc, bias);
    k_keys<<<16, 256>>>();
    dim3 g4((TSIM + 127) / 128, NCHAIN);
    k_thresh<<<g4, 128>>>();
    k_sim<<<NCHAIN, 32>>>(init, fbf, out);
}

// round 3
// speedup vs baseline: 2.5046x; 2.5046x over previous
#include <cuda_runtime.h>
#include <cstdint>
#include <math.h>

// ---------------- problem constants ----------------
#define BATCH   4
#define NPIX    2048
#define NBINS   4096
#define KT      250
#define NREP    64
#define TSIM    3846          // (NBINS - KT + 1) - 1
#define NCHAIN  (BATCH*NREP)  // 256
#define TPAD    3872
#define PCHUNKS 16
#define PPER    (NPIX/PCHUNKS) // 128
#define NCHUNK  ((TSIM + 31) / 32)   // 121

// ---------------- scratch (no allocations allowed) ----------------
__device__ float    d_partial[PCHUNKS][BATCH*NBINS]; // 1 MiB
__device__ float    d_g[BATCH*TPAD];                 // gensig
__device__ uint32_t d_keys[TSIM*2];                  // per-step PRNG keys
__device__ float    d_C[NCHAIN*TPAD];                // logit thresholds, [chain][t]

// ---------------- threefry2x32 (JAX constants, 20 rounds) ----------------
__device__ __forceinline__ void tf2x32(uint32_t k0, uint32_t k1,
                                       uint32_t x0, uint32_t x1,
                                       uint32_t &o0, uint32_t &o1) {
    uint32_t k2 = k0 ^ k1 ^ 0x1BD11BDAu;
#define ROTL(v,s) (((v)<<(s))|((v)>>(32-(s))))
#define RND(r) { x0 += x1; x1 = ROTL(x1,(r)); x1 ^= x0; }
    x0 += k0; x1 += k1;
    RND(13) RND(15) RND(26) RND(6)
    x0 += k1; x1 += k2 + 1u;
    RND(17) RND(29) RND(16) RND(24)
    x0 += k2; x1 += k0 + 2u;
    RND(13) RND(15) RND(26) RND(6)
    x0 += k0; x1 += k1 + 3u;
    RND(17) RND(29) RND(16) RND(24)
    x0 += k1; x1 += k2 + 4u;
    RND(13) RND(15) RND(26) RND(6)
    x0 += k2; x1 += k0 + 5u;
    o0 = x0; o1 = x1;
#undef RND
#undef ROTL
}

// ---------------- K1: spatial projection partials ----------------
__global__ void k_proj(const float* __restrict__ stim, const float* __restrict__ w) {
    int b  = blockIdx.z;
    int pc = blockIdx.y;
    int t0 = blockIdx.x * 1024 + threadIdx.x * 4;
    const float* base = stim + ((size_t)b * NPIX + (size_t)pc * PPER) * NBINS + t0;

    __shared__ float ws[PPER];
    for (int i = threadIdx.x; i < PPER; i += 256) ws[i] = w[pc * PPER + i];
    __syncthreads();

    float4 acc = make_float4(0.f, 0.f, 0.f, 0.f);
#pragma unroll 8
    for (int p = 0; p < PPER; ++p) {
        float4 v = *(const float4*)(base + (size_t)p * NBINS);
        float  c = ws[p];
        acc.x += c * v.x; acc.y += c * v.y; acc.z += c * v.z; acc.w += c * v.w;
    }
    *(float4*)(&d_partial[pc][b * NBINS + t0]) = acc;
}

// ---------------- K2: reduce partials + temporal conv (fp64, bit-identical, wider grid) ----------------
#define CCH 121
__global__ void k_conv(const float* __restrict__ tc, const float* __restrict__ bias) {
    int b  = blockIdx.y;
    int t0 = blockIdx.x * CCH;
    int cnt = min(CCH, TSIM - t0);
    if (cnt <= 0) return;
    int need = cnt + KT - 1;

    __shared__ float sps[CCH + KT];  // 371
    __shared__ float tcs[KT];
    for (int i = threadIdx.x; i < need; i += blockDim.x) {
        float s = 0.f;
        int idx = b * NBINS + t0 + i;
#pragma unroll
        for (int pc = 0; pc < PCHUNKS; ++pc) s += d_partial[pc][idx];
        sps[i] = s;
    }
    for (int i = threadIdx.x; i < KT; i += blockDim.x) tcs[i] = tc[i];
    __syncthreads();

    double bs = (double)bias[0];
    for (int t = threadIdx.x; t < cnt; t += blockDim.x) {
        double a0 = 0.0, a1 = 0.0;
#pragma unroll 2
        for (int k = 0; k < KT; k += 2) {
            a0 += (double)sps[t + k]     * (double)tcs[k];
            a1 += (double)sps[t + k + 1] * (double)tcs[k + 1];
        }
        d_g[b * TPAD + t0 + t] = (float)(a0 + a1 + bs);
    }
}

// ---------------- K3: per-step keys = split(key(42), TSIM) ----------------
__global__ void k_keys() {
    int t = blockIdx.x * 256 + threadIdx.x;
    if (t >= TSIM) return;
    uint32_t o0, o1;
    tf2x32(0u, 42u, 0u, (uint32_t)t, o0, o1);
    d_keys[2*t]   = o0;
    d_keys[2*t+1] = o1;
}

// ---------------- double-float fp32 log of an exact-integer-valued float ----------------
// a in [1, 2^23]. Returns log(mantissa part) as df (lh+ll) and exponent e:
// log(a) = e*ln2 + (lh+ll), with (lh+ll) = log(m), m in [0.75, 1.5].
__device__ __forceinline__ void df_logm(float a, float &lh, float &ll, int &e) {
    int ib = __float_as_int(a);
    e = ((ib >> 23) & 0xff) - 127;
    float m = __int_as_float((ib & 0x007fffff) | 0x3f800000);   // [1,2)
    if (m > 1.5f) { m *= 0.5f; e += 1; }                        // [0.75,1.5]
    // s = (m-1)/(m+1) in double-float
    float num = m - 1.0f;                 // exact (Sterbenz)
    float dh  = m + 1.0f;
    float bv  = dh - m;
    float dl  = (1.0f - bv) + (m - (dh - bv));   // (m+1) = dh + dl exactly
    float q1  = __fdividef(num, dh);
    float rem = fmaf(-q1, dh, num);
    rem       = fmaf(-q1, dl, rem);
    float q2  = __fdividef(rem, dh);
    float sh  = q1 + q2;
    float sl  = q2 - (sh - q1);
    // atanh(s) = s * (1 + w),  w = t/3 + t^2/5 + ...  (t = s^2 <= 0.0295)
    float t = sh * sh;
    float w = fmaf(t, 1.0f/19.0f, 1.0f/17.0f);
    w = fmaf(t, w, 1.0f/15.0f);
    w = fmaf(t, w, 1.0f/13.0f);
    w = fmaf(t, w, 1.0f/11.0f);
    w = fmaf(t, w, 1.0f/9.0f);
    w = fmaf(t, w, 1.0f/7.0f);
    w = fmaf(t, w, 1.0f/5.0f);
    w = fmaf(t, w, 1.0f/3.0f);
    w = w * t;
    // log(m) = 2*atanh(s) = 2s + (2s)*w  in df
    float ph = 2.0f * sh, pl = 2.0f * sl;       // exact doubling
    float qh = ph * w;
    float ql = fmaf(ph, w, -qh);
    ql = fmaf(pl, w, ql);
    lh = ph + qh;                               // Fast2Sum (|ph| >= |qh|)
    ll = ((ph - lh) + qh) + (pl + ql);
}

// ---------------- K4: thresholds c[i][t] = logit(uniform), all fp32 ----------------
__global__ void k_thresh() {
    int t = blockIdx.x * 256 + threadIdx.x;
    int i = blockIdx.y;
    if (t >= TSIM) return;
    uint32_t kk0 = d_keys[2*t], kk1 = d_keys[2*t+1];
    uint32_t o0, o1;
    tf2x32(kk0, kk1, 0u, (uint32_t)i, o0, o1);
    uint32_t bits = o0 ^ o1;
    uint32_t k = bits >> 9;            // u = k * 2^-23 exactly
    float c;
    if (k == 0u) {
        c = -__int_as_float(0x7f800000);   // -inf: always spike
    } else {
        // logit(u) = log(k) - log(2^23 - k)
        float a = (float)k;                 // exact
        float bf = (float)(0x800000u - k);  // exact
        float lah, lal; int ea; df_logm(a,  lah, lal, ea);
        float lbh, lbl; int eb; df_logm(bf, lbh, lbl, eb);
        float de = (float)(ea - eb);
        const float L2H = 0.693145751953125f;   // 12 trailing zero bits: de*L2H exact
        const float L2L = 1.42860682e-6f;       // ln2 - L2H
        // d = logm_a - logm_b  (full 2Sum)
        float s   = lah - lbh;
        float bv2 = s - lah;
        float err = (lah - (s - bv2)) + ((-lbh) - bv2);
        float dl2 = err + (lal - lbl);
        // + de*ln2
        float Eh  = de * L2H;                   // exact
        float th2 = Eh + s;
        float bv3 = th2 - Eh;
        float err2 = (Eh - (th2 - bv3)) + (s - bv3);
        c = th2 + (err2 + dl2 + de * L2L);
    }
    d_C[i * TPAD + t] = c;
}

// ---------------- K5: simulation, 2 warps per chain (far-producer + serial-consumer) ----------------
__global__ void __launch_bounds__(64, 4)
k_sim(const float* __restrict__ initial, const float* __restrict__ fbfilt,
      float* __restrict__ out) {
    int chain = blockIdx.x;          // b*64 + r
    int b     = chain >> 6;
    int tid   = threadIdx.x;
    int lane  = tid & 31;
    int warp  = tid >> 5;

    __shared__ float hist[KT + TSIM + 32];   // full spike history
    __shared__ float fsm[320];               // feedback filter, zero padded
    __shared__ float farbuf[2][32];          // double-buffered far partials

    for (int k = tid; k < 320; k += 64) fsm[k] = (k < KT) ? fbfilt[k] : 0.0f;
    for (int k = tid; k < KT; k += 64) {
        float v = initial[b * KT + k];
        hist[k] = v;
        out[(size_t)chain * NBINS + k] = v;
    }
    __syncthreads();

    const float* gp = d_g + b * TPAD;
    const float* cp = d_C + chain * TPAD;
    float*       op = out + (size_t)chain * NBINS + KT;

    // warp 0: loop-invariant per-lane filter taps in registers
    float fregs[32], nregs[32];
    if (warp == 0) {
#pragma unroll
        for (int m = 0; m < 32; ++m) {
            fregs[m] = fsm[250 - lane + m];   // in-chunk feedback taps (0 for m >= lane)
            nregs[m] = fsm[249 - lane - m];   // near taps (last 32 spikes)
        }
    }

    // prologue: far partials for chunk 0 (taps 32..249, initial window only)
    if (warp == 1) {
        float acc = 0.0f;
        const float* hp = hist + KT - 1;
        int mmax = 249 - lane;
        for (int m = 32; m <= mmax; ++m)
            acc += hp[-m] * fsm[249 - lane - m];
        farbuf[0][lane] = acc;
    }
    __syncthreads();

    for (int i = 0; i < NCHUNK; ++i) {
        if (warp == 0) {
            int t0  = i * 32;
            int len = TSIM - t0; if (len > 32) len = 32;
            float gl = gp[t0 + lane];
            float cl = (lane < len) ? cp[t0 + lane] : __int_as_float(0x7f800000);

            // near contribution: last 32 spikes (previous chunk / initial)
            float nearAcc = 0.0f;
            const float* hp = hist + KT + t0 - 1;
#pragma unroll
            for (int m = 0; m < 32; ++m)
                nearAcc += hp[-m] * nregs[m];

            float fb = (gl + farbuf[i & 1][lane]) + nearAcc;

            // serial resolve: FSETP -> FSEL -> SHFL -> FFMA per step (~38 cyc)
            float myspike = 0.0f;
#pragma unroll
            for (int m = 0; m < 32; ++m) {
                float bitf = (fb > cl) ? 1.0f : 0.0f;
                bitf = __shfl_sync(0xffffffffu, bitf, m);
                fb = fmaf(bitf, fregs[m], fb);
                if (lane == m) myspike = bitf;
            }

            if (lane < len) {
                hist[KT + t0 + lane] = myspike;
                op[t0 + lane]        = myspike;
            }
        } else if (i + 1 < NCHUNK) {
            // far partials for chunk i+1: spikes older than chunk i (already in hist)
            int t0n = (i + 1) * 32;
            float acc = 0.0f;
            const float* hp = hist + KT + t0n - 1;
            int mmax = 249 - lane;
            for (int m = 32; m <= mmax; ++m)
                acc += hp[-m] * fsm[249 - lane - m];
            farbuf[(i + 1) & 1][lane] = acc;
        }
        __syncthreads();
    }
}

// ---------------- launch ----------------
extern "C" void kernel_launch(void* const* d_in, const int* in_sizes, int n_in,
                              void* d_out, int out_size) {
    const float* stim = (const float*)d_in[0];  // (4,2048,4096)
    const float* init = (const float*)d_in[1];  // (4,250)
    const float* spat = (const float*)d_in[2];  // (2048,)
    const float* tc   = (const float*)d_in[3];  // (250,)
    const float* fbf  = (const float*)d_in[4];  // (250,)
    const float* bias = (const float*)d_in[5];  // (1,)
    float* out = (float*)d_out;                 // (4,64,4096) f32

    dim3 g1(4, 16, 4);
    k_proj<<<g1, 256>>>(stim, spat);
    dim3 g2(32, 4);
    k_conv<<<g2, 128>>>(tc, bias);
    k_keys<<<16, 256>>>();
    dim3 g4((TSIM + 255) / 256, NCHAIN);
    k_thresh<<<g4, 256>>>();
    k_sim<<<NCHAIN, 64>>>(init, fbf, out);
}

// round 4
// speedup vs baseline: 4.2354x; 1.6911x over previous
#include <cuda_runtime.h>
#include <cstdint>
#include <math.h>

// ---------------- problem constants ----------------
#define BATCH   4
#define NPIX    2048
#define NBINS   4096
#define KT      250
#define NREP    64
#define TSIM    3846          // (NBINS - KT + 1) - 1
#define NCHAIN  (BATCH*NREP)  // 256
#define TPAD    3872
#define PCHUNKS 16
#define PPER    (NPIX/PCHUNKS) // 128
#define NCHUNK  ((TSIM + 31) / 32)   // 121
#define FPAD    40

// ---------------- scratch (no allocations allowed) ----------------
__device__ float    d_partial[PCHUNKS][BATCH*NBINS]; // 1 MiB
__device__ float    d_g[BATCH*TPAD];                 // gensig (padding stays 0)
__device__ uint32_t d_keys[TSIM*2];                  // per-step PRNG keys
__device__ float    d_C[NCHAIN*TPAD];                // logit thresholds (padding stays 0)

// ---------------- threefry2x32 (JAX constants, 20 rounds) ----------------
__device__ __forceinline__ void tf2x32(uint32_t k0, uint32_t k1,
                                       uint32_t x0, uint32_t x1,
                                       uint32_t &o0, uint32_t &o1) {
    uint32_t k2 = k0 ^ k1 ^ 0x1BD11BDAu;
#define ROTL(v,s) (((v)<<(s))|((v)>>(32-(s))))
#define RND(r) { x0 += x1; x1 = ROTL(x1,(r)); x1 ^= x0; }
    x0 += k0; x1 += k1;
    RND(13) RND(15) RND(26) RND(6)
    x0 += k1; x1 += k2 + 1u;
    RND(17) RND(29) RND(16) RND(24)
    x0 += k2; x1 += k0 + 2u;
    RND(13) RND(15) RND(26) RND(6)
    x0 += k0; x1 += k1 + 3u;
    RND(17) RND(29) RND(16) RND(24)
    x0 += k1; x1 += k2 + 4u;
    RND(13) RND(15) RND(26) RND(6)
    x0 += k2; x1 += k0 + 5u;
    o0 = x0; o1 = x1;
#undef RND
#undef ROTL
}

// ---------------- K1: spatial projection partials ----------------
// grid (8 t-tiles, 16 p-chunks, 4 b), block 128, float4 per thread.
__global__ void k_proj(const float* __restrict__ stim, const float* __restrict__ w) {
    int b  = blockIdx.z;
    int pc = blockIdx.y;
    int t0 = blockIdx.x * 512 + threadIdx.x * 4;
    const float* base = stim + ((size_t)b * NPIX + (size_t)pc * PPER) * NBINS + t0;

    __shared__ float ws[PPER];
    if (threadIdx.x < PPER) ws[threadIdx.x] = w[pc * PPER + threadIdx.x];
    __syncthreads();

    float4 acc = make_float4(0.f, 0.f, 0.f, 0.f);
#pragma unroll 8
    for (int p = 0; p < PPER; ++p) {
        float4 v = *(const float4*)(base + (size_t)p * NBINS);
        float  c = ws[p];
        acc.x += c * v.x; acc.y += c * v.y; acc.z += c * v.z; acc.w += c * v.w;
    }
    *(float4*)(&d_partial[pc][b * NBINS + t0]) = acc;
}

// ---------------- K2: reduce partials + temporal conv (fp64, bit-identical) ----------------
#define CCH 121
__global__ void k_conv(const float* __restrict__ tc, const float* __restrict__ bias) {
    int b  = blockIdx.y;
    int t0 = blockIdx.x * CCH;
    int cnt = min(CCH, TSIM - t0);
    if (cnt <= 0) return;
    int need = cnt + KT - 1;

    __shared__ float sps[CCH + KT];
    __shared__ float tcs[KT];
    for (int i = threadIdx.x; i < need; i += blockDim.x) {
        float s = 0.f;
        int idx = b * NBINS + t0 + i;
#pragma unroll
        for (int pc = 0; pc < PCHUNKS; ++pc) s += d_partial[pc][idx];
        sps[i] = s;
    }
    for (int i = threadIdx.x; i < KT; i += blockDim.x) tcs[i] = tc[i];
    __syncthreads();

    double bs = (double)bias[0];
    for (int t = threadIdx.x; t < cnt; t += blockDim.x) {
        double a0 = 0.0, a1 = 0.0;
#pragma unroll 2
        for (int k = 0; k < KT; k += 2) {
            a0 += (double)sps[t + k]     * (double)tcs[k];
            a1 += (double)sps[t + k + 1] * (double)tcs[k + 1];
        }
        d_g[b * TPAD + t0 + t] = (float)(a0 + a1 + bs);
    }
}

// ---------------- K3: per-step keys = split(key(42), TSIM) ----------------
__global__ void k_keys() {
    int t = blockIdx.x * 256 + threadIdx.x;
    if (t >= TSIM) return;
    uint32_t o0, o1;
    tf2x32(0u, 42u, 0u, (uint32_t)t, o0, o1);
    d_keys[2*t]   = o0;
    d_keys[2*t+1] = o1;
}

// ---------------- double-float fp32 log of exact-integer-valued float ----------------
__device__ __forceinline__ void df_logm(float a, float &lh, float &ll, int &e) {
    int ib = __float_as_int(a);
    e = ((ib >> 23) & 0xff) - 127;
    float m = __int_as_float((ib & 0x007fffff) | 0x3f800000);
    if (m > 1.5f) { m *= 0.5f; e += 1; }
    float num = m - 1.0f;
    float dh  = m + 1.0f;
    float bv  = dh - m;
    float dl  = (1.0f - bv) + (m - (dh - bv));
    float q1  = __fdividef(num, dh);
    float rem = fmaf(-q1, dh, num);
    rem       = fmaf(-q1, dl, rem);
    float q2  = __fdividef(rem, dh);
    float sh  = q1 + q2;
    float sl  = q2 - (sh - q1);
    float t = sh * sh;
    float w = fmaf(t, 1.0f/19.0f, 1.0f/17.0f);
    w = fmaf(t, w, 1.0f/15.0f);
    w = fmaf(t, w, 1.0f/13.0f);
    w = fmaf(t, w, 1.0f/11.0f);
    w = fmaf(t, w, 1.0f/9.0f);
    w = fmaf(t, w, 1.0f/7.0f);
    w = fmaf(t, w, 1.0f/5.0f);
    w = fmaf(t, w, 1.0f/3.0f);
    w = w * t;
    float ph = 2.0f * sh, pl = 2.0f * sl;
    float qh = ph * w;
    float ql = fmaf(ph, w, -qh);
    ql = fmaf(pl, w, ql);
    lh = ph + qh;
    ll = ((ph - lh) + qh) + (pl + ql);
}

// ---------------- K4: thresholds c[i][t] = logit(uniform), all fp32 ----------------
__global__ void k_thresh() {
    int t = blockIdx.x * 256 + threadIdx.x;
    int i = blockIdx.y;
    if (t >= TSIM) return;
    uint32_t kk0 = d_keys[2*t], kk1 = d_keys[2*t+1];
    uint32_t o0, o1;
    tf2x32(kk0, kk1, 0u, (uint32_t)i, o0, o1);
    uint32_t bits = o0 ^ o1;
    uint32_t k = bits >> 9;
    float c;
    if (k == 0u) {
        c = -__int_as_float(0x7f800000);
    } else {
        float a = (float)k;
        float bf = (float)(0x800000u - k);
        float lah, lal; int ea; df_logm(a,  lah, lal, ea);
        float lbh, lbl; int eb; df_logm(bf, lbh, lbl, eb);
        float de = (float)(ea - eb);
        const float L2H = 0.693145751953125f;
        const float L2L = 1.42860682e-6f;
        float s   = lah - lbh;
        float bv2 = s - lah;
        float err = (lah - (s - bv2)) + ((-lbh) - bv2);
        float dl2 = err + (lal - lbl);
        float Eh  = de * L2H;
        float th2 = Eh + s;
        float bv3 = th2 - Eh;
        float err2 = (Eh - (th2 - bv3)) + (s - bv3);
        c = th2 + (err2 + dl2 + de * L2L);
    }
    d_C[i * TPAD + t] = c;
}

// ---------------- K5: simulation ----------------
// 5 warps/block: warp 0 = consumer (group-speculative resolve), warps 1-4 = far-dot producers.
__global__ void __launch_bounds__(160, 2)
k_sim(const float* __restrict__ initial, const float* __restrict__ fbfilt,
      float* __restrict__ out) {
    int chain = blockIdx.x;          // b*64 + r
    int b     = chain >> 6;
    int tid   = threadIdx.x;
    int lane  = tid & 31;
    int warp  = tid >> 5;

    __shared__ float hist[KT + TSIM + 40];   // spike history (initial + simulated)
    __shared__ float fsmp[FPAD + 256];       // padded feedback filter: fsmp[FPAD+i]=f[i]
    __shared__ float part[2][4][32];         // double-buffered far partials

    for (int k = tid; k < FPAD + 256; k += 160) {
        int i = k - FPAD;
        fsmp[k] = (i >= 0 && i < KT) ? fbfilt[i] : 0.0f;
    }
    for (int k = tid; k < KT; k += 160) {
        float v = initial[b * KT + k];
        hist[k] = v;
        out[(size_t)chain * NBINS + k] = v;
    }
    __syncthreads();

    const float* gp = d_g + b * TPAD;
    const float* cp = d_C + chain * TPAD;
    float*       op = out + (size_t)chain * NBINS + KT;

    if (warp == 0) {
        // ---- consumer ----
        int fbits[32], nbits[32], wb[8];
#pragma unroll
        for (int s = 0; s < 32; ++s) {
            // tap applied to lane l's step from in-chunk bit s (distance l-s)
            fbits[s] = (lane > s) ? __float_as_int(fsmp[FPAD + 250 - (lane - s)]) : 0;
            // tap applied to lane l's step from previous-chunk bit s (distance 32-s+l)
            nbits[s] = __float_as_int(fsmp[FPAD + 218 + s - lane]);
        }
#pragma unroll
        for (int d = 1; d < 8; ++d) wb[d] = __float_as_int(fsmp[FPAD + 250 - d]);

        // prologue: carry from initial window's last 32 spikes
        float c0 = 0.f, c1 = 0.f, c2 = 0.f, c3 = 0.f;
#pragma unroll
        for (int s = 0; s < 32; s += 4) {
            c0 = fmaf(hist[KT - 32 + s],     __int_as_float(nbits[s]),     c0);
            c1 = fmaf(hist[KT - 31 + s],     __int_as_float(nbits[s + 1]), c1);
            c2 = fmaf(hist[KT - 30 + s],     __int_as_float(nbits[s + 2]), c2);
            c3 = fmaf(hist[KT - 29 + s],     __int_as_float(nbits[s + 3]), c3);
        }
        float carry = (c0 + c1) + (c2 + c3);
        float gl = __ldg(gp + lane);
        float cl = __ldg(cp + lane);
        __syncthreads();   // pairs with producers' prologue sync

        for (int i = 0; i < NCHUNK; ++i) {
            int t0 = i * 32;
            // prefetch next chunk's g/c early (hidden under resolve)
            int nidx = t0 + 32 + lane; if (nidx > TPAD - 1) nidx = TPAD - 1;
            float gl2 = __ldg(gp + nidx);
            float cl2 = __ldg(cp + nidx);

            float farsum = (part[i & 1][0][lane] + part[i & 1][1][lane])
                         + (part[i & 1][2][lane] + part[i & 1][3][lane]);
            float y = ((gl + farsum) + carry) - cl;   // margin vs threshold

            unsigned bw = 0u;
#pragma unroll
            for (int grp = 0; grp < 4; ++grp) {
                float z[8];
#pragma unroll
                for (int j = 0; j < 8; ++j)
                    z[j] = __shfl_sync(0xffffffffu, y, grp * 8 + j);
                int gm[8];
#pragma unroll
                for (int j = 0; j < 8; ++j) {
                    int msk = (-__float_as_int(z[j])) >> 31;   // -1 iff z>0 (spike)
                    gm[j] = msk;
#pragma unroll
                    for (int d = 1; d < 8 - j; ++d)
                        z[j + d] += __int_as_float(msk & wb[d]);
                }
#pragma unroll
                for (int j = 0; j < 8; ++j) {
                    y += __int_as_float(gm[j] & fbits[grp * 8 + j]);
                    bw |= ((unsigned)gm[j]) & (1u << (grp * 8 + j));
                }
            }

            float spikef = (float)((bw >> lane) & 1u);
            hist[KT + t0 + lane] = spikef;
            if (t0 + lane < TSIM) op[t0 + lane] = spikef;

            // carry for next chunk from this chunk's packed masks
            float a0 = 0.f, a1 = 0.f, a2 = 0.f, a3 = 0.f;
#pragma unroll
            for (int s = 0; s < 32; s += 4) {
                a0 += __int_as_float((((int)(bw << (31 - s))) >> 31) & nbits[s]);
                a1 += __int_as_float((((int)(bw << (30 - s))) >> 31) & nbits[s + 1]);
                a2 += __int_as_float((((int)(bw << (29 - s))) >> 31) & nbits[s + 2]);
                a3 += __int_as_float((((int)(bw << (28 - s))) >> 31) & nbits[s + 3]);
            }
            carry = (a0 + a1) + (a2 + a3);
            gl = gl2; cl = cl2;
            __syncthreads();
        }
    } else {
        // ---- producers: far feedback (taps m=32..249), stride-4 split across 4 warps ----
        int pw = warp - 1;   // 0..3
        {
            float acc = 0.0f;
            const float* hp = hist + KT - 1;
#pragma unroll
            for (int k = 0; k < 54; ++k) {
                int m = 32 + pw + 4 * k;                       // <= 247
                acc = fmaf(hp[-m], fsmp[FPAD + 249 - lane - m], acc);
            }
            if (pw < 2) {
                int m = 248 + pw;
                acc = fmaf(hp[-m], fsmp[FPAD + 249 - lane - m], acc);
            }
            part[0][pw][lane] = acc;
        }
        __syncthreads();

        for (int i = 0; i < NCHUNK; ++i) {
            if (i + 1 < NCHUNK) {
                int t0n = (i + 1) * 32;
                float acc = 0.0f;
                const float* hp = hist + KT + t0n - 1;
#pragma unroll
                for (int k = 0; k < 54; ++k) {
                    int m = 32 + pw + 4 * k;
                    acc = fmaf(hp[-m], fsmp[FPAD + 249 - lane - m], acc);
                }
                if (pw < 2) {
                    int m = 248 + pw;
                    acc = fmaf(hp[-m], fsmp[FPAD + 249 - lane - m], acc);
                }
                part[(i + 1) & 1][pw][lane] = acc;
            }
            __syncthreads();
        }
    }
}

// ---------------- launch ----------------
extern "C" void kernel_launch(void* const* d_in, const int* in_sizes, int n_in,
                              void* d_out, int out_size) {
    const float* stim = (const float*)d_in[0];  // (4,2048,4096)
    const float* init = (const float*)d_in[1];  // (4,250)
    const float* spat = (const float*)d_in[2];  // (2048,)
    const float* tc   = (const float*)d_in[3];  // (250,)
    const float* fbf  = (const float*)d_in[4];  // (250,)
    const float* bias = (const float*)d_in[5];  // (1,)
    float* out = (float*)d_out;                 // (4,64,4096) f32

    dim3 g1(8, 16, 4);
    k_proj<<<g1, 128>>>(stim, spat);
    dim3 g2(32, 4);
    k_conv<<<g2, 128>>>(tc, bias);
    k_keys<<<16, 256>>>();
    dim3 g4((TSIM + 255) / 256, NCHAIN);
    k_thresh<<<g4, 256>>>();
    k_sim<<<NCHAIN, 160>>>(init, fbf, out);
}

// round 5
// speedup vs baseline: 4.3435x; 1.0255x over previous
#include <cuda_runtime.h>
#include <cstdint>
#include <math.h>

// ---------------- problem constants ----------------
#define BATCH   4
#define NPIX    2048
#define NBINS   4096
#define KT      250
#define NREP    64
#define TSIM    3846          // (NBINS - KT + 1) - 1
#define NCHAIN  (BATCH*NREP)  // 256
#define TPAD    3872
#define PCHUNKS 16
#define PPER    (NPIX/PCHUNKS) // 128
#define NCHUNK  ((TSIM + 31) / 32)   // 121
#define FPAD    40

// ---------------- scratch (no allocations allowed) ----------------
__device__ float    d_partial[PCHUNKS][BATCH*NBINS]; // 1 MiB
__device__ float    d_g[BATCH*TPAD];                 // gensig (padding stays 0)
__device__ uint32_t d_keys[TSIM*2];                  // per-step PRNG keys
__device__ float    d_C[NCHAIN*TPAD];                // logit thresholds (padding stays 0)

// ---------------- threefry2x32 (JAX constants, 20 rounds) ----------------
__device__ __forceinline__ void tf2x32(uint32_t k0, uint32_t k1,
                                       uint32_t x0, uint32_t x1,
                                       uint32_t &o0, uint32_t &o1) {
    uint32_t k2 = k0 ^ k1 ^ 0x1BD11BDAu;
#define ROTL(v,s) (((v)<<(s))|((v)>>(32-(s))))
#define RND(r) { x0 += x1; x1 = ROTL(x1,(r)); x1 ^= x0; }
    x0 += k0; x1 += k1;
    RND(13) RND(15) RND(26) RND(6)
    x0 += k1; x1 += k2 + 1u;
    RND(17) RND(29) RND(16) RND(24)
    x0 += k2; x1 += k0 + 2u;
    RND(13) RND(15) RND(26) RND(6)
    x0 += k0; x1 += k1 + 3u;
    RND(17) RND(29) RND(16) RND(24)
    x0 += k1; x1 += k2 + 4u;
    RND(13) RND(15) RND(26) RND(6)
    x0 += k2; x1 += k0 + 5u;
    o0 = x0; o1 = x1;
#undef RND
#undef ROTL
}

// ---------------- K1: spatial projection partials ----------------
__global__ void k_proj(const float* __restrict__ stim, const float* __restrict__ w) {
    int b  = blockIdx.z;
    int pc = blockIdx.y;
    int t0 = blockIdx.x * 512 + threadIdx.x * 4;
    const float* base = stim + ((size_t)b * NPIX + (size_t)pc * PPER) * NBINS + t0;

    __shared__ float ws[PPER];
    if (threadIdx.x < PPER) ws[threadIdx.x] = w[pc * PPER + threadIdx.x];
    __syncthreads();

    float4 acc = make_float4(0.f, 0.f, 0.f, 0.f);
#pragma unroll 8
    for (int p = 0; p < PPER; ++p) {
        float4 v = *(const float4*)(base + (size_t)p * NBINS);
        float  c = ws[p];
        acc.x += c * v.x; acc.y += c * v.y; acc.z += c * v.z; acc.w += c * v.w;
    }
    *(float4*)(&d_partial[pc][b * NBINS + t0]) = acc;
}

// ---------------- K2: reduce partials + temporal conv (fp64, 8 accumulators) ----------------
#define CCH 121
__global__ void k_conv(const float* __restrict__ tc, const float* __restrict__ bias) {
    int b  = blockIdx.y;
    int t0 = blockIdx.x * CCH;
    int cnt = min(CCH, TSIM - t0);
    if (cnt <= 0) return;
    int need = cnt + KT - 1;

    __shared__ float sps[CCH + KT];
    __shared__ float tcs[KT + 6];
    for (int i = threadIdx.x; i < need; i += blockDim.x) {
        float s = 0.f;
        int idx = b * NBINS + t0 + i;
#pragma unroll
        for (int pc = 0; pc < PCHUNKS; ++pc) s += d_partial[pc][idx];
        sps[i] = s;
    }
    for (int i = threadIdx.x; i < KT + 6; i += blockDim.x) tcs[i] = (i < KT) ? tc[i] : 0.0f;
    __syncthreads();

    double bs = (double)bias[0];
    for (int t = threadIdx.x; t < cnt; t += blockDim.x) {
        double a[8];
#pragma unroll
        for (int j = 0; j < 8; ++j) a[j] = 0.0;
#pragma unroll 4
        for (int k = 0; k < KT; k += 8) {
#pragma unroll
            for (int j = 0; j < 8; ++j)
                if (k + j < KT) a[j] += (double)sps[t + k + j] * (double)tcs[k + j];
        }
        double s = ((a[0] + a[1]) + (a[2] + a[3])) + ((a[4] + a[5]) + (a[6] + a[7]));
        d_g[b * TPAD + t0 + t] = (float)(s + bs);
    }
}

// ---------------- K3: per-step keys = split(key(42), TSIM) ----------------
__global__ void k_keys() {
    int t = blockIdx.x * 256 + threadIdx.x;
    if (t >= TSIM) return;
    uint32_t o0, o1;
    tf2x32(0u, 42u, 0u, (uint32_t)t, o0, o1);
    d_keys[2*t]   = o0;
    d_keys[2*t+1] = o1;
}

// ---------------- double-float fp32 log of exact-integer-valued float ----------------
__device__ __forceinline__ void df_logm(float a, float &lh, float &ll, int &e) {
    int ib = __float_as_int(a);
    e = ((ib >> 23) & 0xff) - 127;
    float m = __int_as_float((ib & 0x007fffff) | 0x3f800000);
    if (m > 1.5f) { m *= 0.5f; e += 1; }
    float num = m - 1.0f;
    float dh  = m + 1.0f;
    float bv  = dh - m;
    float dl  = (1.0f - bv) + (m - (dh - bv));
    float q1  = __fdividef(num, dh);
    float rem = fmaf(-q1, dh, num);
    rem       = fmaf(-q1, dl, rem);
    float q2  = __fdividef(rem, dh);
    float sh  = q1 + q2;
    float sl  = q2 - (sh - q1);
    float t = sh * sh;
    float w = fmaf(t, 1.0f/19.0f, 1.0f/17.0f);
    w = fmaf(t, w, 1.0f/15.0f);
    w = fmaf(t, w, 1.0f/13.0f);
    w = fmaf(t, w, 1.0f/11.0f);
    w = fmaf(t, w, 1.0f/9.0f);
    w = fmaf(t, w, 1.0f/7.0f);
    w = fmaf(t, w, 1.0f/5.0f);
    w = fmaf(t, w, 1.0f/3.0f);
    w = w * t;
    float ph = 2.0f * sh, pl = 2.0f * sl;
    float qh = ph * w;
    float ql = fmaf(ph, w, -qh);
    ql = fmaf(pl, w, ql);
    lh = ph + qh;
    ll = ((ph - lh) + qh) + (pl + ql);
}

// ---------------- K4: thresholds c[i][t] = logit(uniform), all fp32 ----------------
__global__ void k_thresh() {
    int t = blockIdx.x * 256 + threadIdx.x;
    int i = blockIdx.y;
    if (t >= TSIM) return;
    uint32_t kk0 = d_keys[2*t], kk1 = d_keys[2*t+1];
    uint32_t o0, o1;
    tf2x32(kk0, kk1, 0u, (uint32_t)i, o0, o1);
    uint32_t bits = o0 ^ o1;
    uint32_t k = bits >> 9;
    float c;
    if (k == 0u) {
        c = -__int_as_float(0x7f800000);
    } else {
        float a = (float)k;
        float bf = (float)(0x800000u - k);
        float lah, lal; int ea; df_logm(a,  lah, lal, ea);
        float lbh, lbl; int eb; df_logm(bf, lbh, lbl, eb);
        float de = (float)(ea - eb);
        const float L2H = 0.693145751953125f;
        const float L2L = 1.42860682e-6f;
        float s   = lah - lbh;
        float bv2 = s - lah;
        float err = (lah - (s - bv2)) + ((-lbh) - bv2);
        float dl2 = err + (lal - lbl);
        float Eh  = de * L2H;
        float th2 = Eh + s;
        float bv3 = th2 - Eh;
        float err2 = (Eh - (th2 - bv3)) + (s - bv3);
        c = th2 + (err2 + dl2 + de * L2L);
    }
    d_C[i * TPAD + t] = c;
}

// ---------------- K5: simulation ----------------
// Negated margin v = c - x: spike <=> sign(v). All feedback taps pre-negated (positive).
// warp 0 = consumer (sign+LOP3 select chain), warps 1-4 = ybase producers.
__global__ void __launch_bounds__(160, 2)
k_sim(const float* __restrict__ initial, const float* __restrict__ fbfilt,
      float* __restrict__ out) {
    int chain = blockIdx.x;          // b*64 + r
    int b     = chain >> 6;
    int tid   = threadIdx.x;
    int lane  = tid & 31;
    int warp  = tid >> 5;

    __shared__ float histbuf[8 + KT + TSIM + 40];
    __shared__ float fsnp[FPAD + 256];     // NEGATED padded feedback filter
    __shared__ float ybuf[2][32];          // double-buffered ybase = c - g + far(negated)

    float* hist = histbuf + 8;

    for (int k = tid; k < FPAD + 256; k += 160) {
        int i = k - FPAD;
        fsnp[k] = (i >= 0 && i < KT) ? -fbfilt[i] : 0.0f;
    }
    for (int k = tid; k < 8; k += 160) histbuf[k] = 0.0f;
    for (int k = tid; k < KT; k += 160) {
        float v = initial[b * KT + k];
        hist[k] = v;
        out[(size_t)chain * NBINS + k] = v;
    }
    __syncthreads();

    const float* gp = d_g + b * TPAD;
    const float* cp = d_C + chain * TPAD;
    float*       op = out + (size_t)chain * NBINS + KT;

    if (warp == 0) {
        // ---- consumer ----
        int   nfb[32], ncb[32];   // bit-patterns of negated taps
        float wbf[8];
#pragma unroll
        for (int s = 0; s < 32; ++s) {
            nfb[s] = (lane > s) ? __float_as_int(fsnp[FPAD + 250 - lane + s]) : 0;
            ncb[s] = __float_as_int(fsnp[FPAD + 218 + s - lane]);
        }
#pragma unroll
        for (int d = 1; d < 8; ++d) wbf[d] = fsnp[FPAD + 250 - d];

        // initial carry from last 32 initial-window spikes (positive taps)
        float c0 = 0.f, c1 = 0.f, c2 = 0.f, c3 = 0.f;
#pragma unroll
        for (int s = 0; s < 32; s += 4) {
            c0 = fmaf(hist[KT - 32 + s],     __int_as_float(ncb[s]),     c0);
            c1 = fmaf(hist[KT - 31 + s],     __int_as_float(ncb[s + 1]), c1);
            c2 = fmaf(hist[KT - 30 + s],     __int_as_float(ncb[s + 2]), c2);
            c3 = fmaf(hist[KT - 29 + s],     __int_as_float(ncb[s + 3]), c3);
        }
        float carry = (c0 + c1) + (c2 + c3);
        __syncthreads();   // ybuf[0] ready

        for (int i = 0; i < NCHUNK; ++i) {
            int t0 = i * 32;
            float v = ybuf[i & 1][lane] + carry;   // negated margin; spike <=> v<0

            unsigned bw = 0u;
            float k0s = 0.f, k1s = 0.f, k2s = 0.f, k3s = 0.f;
#pragma unroll
            for (int grp = 0; grp < 4; ++grp) {
                int u[8];
#pragma unroll
                for (int j = 0; j < 8; ++j)
                    u[j] = __float_as_int(__shfl_sync(0xffffffffu, v, grp * 8 + j));
                int gm[8];
#pragma unroll
                for (int j = 0; j < 8; ++j) {
                    int msk = u[j] >> 31;                 // -1 iff spike
                    gm[j] = msk;
#pragma unroll
                    for (int d = 1; d < 8 - j; ++d) {
                        int cand = __float_as_int(__int_as_float(u[j + d]) + wbf[d]);
                        u[j + d] = (cand & msk) | (u[j + d] & ~msk);
                    }
                }
                // y-correction for later groups (tree)
                int base = grp * 8;
                float s0 = __int_as_float(gm[0] & nfb[base])     + __int_as_float(gm[1] & nfb[base + 1]);
                float s1 = __int_as_float(gm[2] & nfb[base + 2]) + __int_as_float(gm[3] & nfb[base + 3]);
                float s2 = __int_as_float(gm[4] & nfb[base + 4]) + __int_as_float(gm[5] & nfb[base + 5]);
                float s3 = __int_as_float(gm[6] & nfb[base + 6]) + __int_as_float(gm[7] & nfb[base + 7]);
                v += (s0 + s1) + (s2 + s3);
                // carry fold for next chunk (off critical path)
                k0s += __int_as_float(gm[0] & ncb[base])     + __int_as_float(gm[4] & ncb[base + 4]);
                k1s += __int_as_float(gm[1] & ncb[base + 1]) + __int_as_float(gm[5] & ncb[base + 5]);
                k2s += __int_as_float(gm[2] & ncb[base + 2]) + __int_as_float(gm[6] & ncb[base + 6]);
                k3s += __int_as_float(gm[3] & ncb[base + 3]) + __int_as_float(gm[7] & ncb[base + 7]);
                // spike bits
                bw |= (gm[0] & (1u << base))       | (gm[1] & (2u << base))
                    | (gm[2] & (4u << base))       | (gm[3] & (8u << base))
                    | (gm[4] & (16u << base))      | (gm[5] & (32u << base))
                    | (gm[6] & (64u << base))      | (gm[7] & (128u << base));
            }
            carry = (k0s + k1s) + (k2s + k3s);

            float spikef = (float)((bw >> lane) & 1u);
            hist[KT + t0 + lane] = spikef;
            if (t0 + lane < TSIM) op[t0 + lane] = spikef;
            __syncthreads();
        }
    } else {
        // ---- producers: ybase[step] = (c - g) + sum_{m>=32} hist*(-f) ----
        int pw = warp - 1;           // 0..3
        int s  = pw * 8 + (lane & 7);
        int q  = lane >> 3;

        // prologue: chunk 0
        {
            int t0n = 0;
            float gl = 0.f, cl = 0.f;
            if (lane < 8) { gl = __ldg(gp + t0n + s); cl = __ldg(cp + t0n + s); }
            float acc = 0.0f;
            const float* hp = hist + KT + t0n - 1;
            const float* fp = fsnp + FPAD + 249 - s;
#pragma unroll
            for (int k = 0; k < 55; ++k) {
                int m = 32 + q + 4 * k;
                acc = fmaf(hp[-m], fp[-m], acc);
            }
            acc += __shfl_xor_sync(0xffffffffu, acc, 8);
            acc += __shfl_xor_sync(0xffffffffu, acc, 16);
            if (lane < 8) ybuf[0][s] = (cl - gl) + acc;
        }
        __syncthreads();

        for (int i = 0; i < NCHUNK; ++i) {
            if (i + 1 < NCHUNK) {
                int t0n = (i + 1) * 32;
                float gl = 0.f, cl = 0.f;
                if (lane < 8) { gl = __ldg(gp + t0n + s); cl = __ldg(cp + t0n + s); }
                float acc = 0.0f;
                const float* hp = hist + KT + t0n - 1;
                const float* fp = fsnp + FPAD + 249 - s;
#pragma unroll
                for (int k = 0; k < 55; ++k) {
                    int m = 32 + q + 4 * k;
                    acc = fmaf(hp[-m], fp[-m], acc);
                }
                acc += __shfl_xor_sync(0xffffffffu, acc, 8);
                acc += __shfl_xor_sync(0xffffffffu, acc, 16);
                if (lane < 8) ybuf[(i + 1) & 1][s] = (cl - gl) + acc;
            }
            __syncthreads();
        }
    }
}

// ---------------- launch ----------------
extern "C" void kernel_launch(void* const* d_in, const int* in_sizes, int n_in,
                              void* d_out, int out_size) {
    const float* stim = (const float*)d_in[0];  // (4,2048,4096)
    const float* init = (const float*)d_in[1];  // (4,250)
    const float* spat = (const float*)d_in[2];  // (2048,)
    const float* tc   = (const float*)d_in[3];  // (250,)
    const float* fbf  = (const float*)d_in[4];  // (250,)
    const float* bias = (const float*)d_in[5];  // (1,)
    float* out = (float*)d_out;                 // (4,64,4096) f32

    dim3 g1(8, 16, 4);
    k_proj<<<g1, 128>>>(stim, spat);
    dim3 g2(32, 4);
    k_conv<<<g2, 128>>>(tc, bias);
    k_keys<<<16, 256>>>();
    dim3 g4((TSIM + 255) / 256, NCHAIN);
    k_thresh<<<g4, 256>>>();
    k_sim<<<NCHAIN, 160>>>(init, fbf, out);
}